// round 8
// baseline (speedup 1.0000x reference)
#include <cuda_runtime.h>
#include <cuda_bf16.h>

// GPTQLinear: out[16,11008] = x[16,4096] @ W^T + bias, W = (q - z) * s, int4 groups of 128.
// Inputs: x f32[16,4096], qweight i32[11008,2048] (one byte/elem, 2 nibbles),
// scales f32[11008,32], zeros f32[11008,32], bias f32[11008]. Output f32[16,11008].

#define OUTF  11008
#define INF   4096
#define NB    16
#define QI    2048
#define NG    32
#define ROWS_PER_WARP 4
#define WARPS 4
#define THREADS 128
#define ROWS_PER_BLOCK 16
#define NBLOCKS (OUTF / ROWS_PER_BLOCK)          // 688
#define CHUNK_COLS 256
#define CHUNK_F4 1024                            // float4 per x chunk (16KB)
#define NCHUNKS 16
#define TITERS 4
#define TT_TOTAL 64                              // total 64-col granules

// smem: x[2][16KB] | qw ring[4][2KB] | sb[4KB]  = 45056 B (occ 5: 5*45KB <= 228KB)
#define SM_X(buf)   ((buf) << 14)
#define SM_QW(slot) (32768 + ((slot) << 11))
#define SM_SB       40960
#define SM_TOTAL    45056

typedef unsigned long long ull;

__device__ float4 g_xpack[QI * 8];               // xT[4096][16], PRE-SWIZZLED per 8KB chunk
__device__ float2 g_sB[OUTF * NG];               // {s, -z*s}

#define FMA2(acc, a, b) asm("fma.rn.f32x2 %0, %1, %2, %0;" : "+l"(acc) : "l"(a), "l"(b))
#define ADD2(d, a, b)   asm("add.rn.f32x2 %0, %1, %2;" : "=l"(d) : "l"(a), "l"(b))
#define PACKW(d, w) do { unsigned _wu = __float_as_uint(w); \
    asm("mov.b64 %0, {%1, %1};" : "=l"(d) : "r"(_wu)); } while (0)

__device__ __forceinline__ void cp16(unsigned dst, const void* src) {
    asm volatile("cp.async.cg.shared.global [%0], [%1], 16;" :: "r"(dst), "l"(src));
}
#define CP_COMMIT() asm volatile("cp.async.commit_group;")
#define CP_WAIT(n)  asm volatile("cp.async.wait_group %0;" :: "n"(n))

// Fused prep: blocks [0,64) transpose x into PRE-SWIZZLED g_xpack; rest build {s,-z*s}.
__global__ void prep_kernel(const float* __restrict__ x,
                            const float* __restrict__ scales,
                            const float* __restrict__ zeros) {
    if (blockIdx.x < 64) {
        __shared__ float tile[NB][65];
        const int c0 = blockIdx.x * 64;
        const int tid = threadIdx.x;
#pragma unroll
        for (int idx = tid; idx < NB * 64; idx += 256) {
            int r = idx >> 6, col = idx & 63;
            tile[r][col] = x[r * INF + c0 + col];
        }
        __syncthreads();
        float* xo = reinterpret_cast<float*>(g_xpack);
#pragma unroll
        for (int idx = tid; idx < NB * 64; idx += 256) {
            int col = idx >> 4, b = idx & 15;
            int j  = (c0 + col) * 4 + (b >> 2);           // float4 index
            int jl = j & 1023;                            // within 16KB chunk
            int dj = (j & ~1023) | (jl ^ ((jl >> 3) & 7)); // bake chunk-local swizzle
            xo[dj * 4 + (b & 3)] = tile[b][col];
        }
    } else {
        int i = (blockIdx.x - 64) * 256 + threadIdx.x;
        float s = scales[i];
        float z = zeros[i];
        g_sB[i] = make_float2(s, -z * s);
    }
}

__global__ __launch_bounds__(THREADS, 5)
void gptq_main_kernel(const int* __restrict__ qw,
                      const float* __restrict__ bias,
                      float* __restrict__ out) {
    __shared__ __align__(128) char smem_raw[SM_TOTAL];

    const int tid  = threadIdx.x;
    const int lane = tid & 31;
    const int warp = tid >> 5;
    const int rb0  = blockIdx.x * ROWS_PER_BLOCK;
    const int o0   = rb0 + warp * ROWS_PER_WARP;
    const int xr   = lane & 7;

    unsigned sm;
    asm("{ .reg .u64 t; cvta.to.shared.u64 t, %1; cvt.u32.u64 %0, t; }"
        : "=r"(sm) : "l"(smem_raw));

    // qw staging: lane l stages row (l>>3), 16B piece (l&7) of each 64-col granule
    const int* qsrc = qw + (o0 + (lane >> 3)) * QI + ((lane & 7) << 2);
    const unsigned qdst = sm + 32768 + (unsigned)(warp * 512 + (lane >> 3) * 128
                                                  + (lane & 7) * 16);

    const float4* gxp = g_xpack;

    // ---- prologue: group X0 = {x chunk 0 + scale table}, then qw granules 0..3 ----
#pragma unroll
    for (int i = 0; i < 8; ++i) {
        int idx = tid + i * THREADS;
        cp16(sm + SM_X(0) + (unsigned)(idx * 16), gxp + idx);
    }
    {
        const char* gsb = reinterpret_cast<const char*>(g_sB + rb0 * NG);
        cp16(sm + SM_SB + (unsigned)(tid * 32),      gsb + tid * 32);
        cp16(sm + SM_SB + (unsigned)(tid * 32 + 16), gsb + tid * 32 + 16);
    }
    CP_COMMIT();
    gxp += CHUNK_F4;
#pragma unroll
    for (int g = 0; g < 4; ++g) {
        cp16(qdst + (unsigned)(g << 11), qsrc);
        qsrc += 32;
        CP_COMMIT();
    }

    ull acc[ROWS_PER_WARP][8];
#pragma unroll
    for (int r = 0; r < ROWS_PER_WARP; ++r)
#pragma unroll
        for (int k = 0; k < 8; ++k) acc[r][k] = 0ull;

    const float2* s_sb = reinterpret_cast<const float2*>(smem_raw + SM_SB)
                         + (warp * ROWS_PER_WARP) * NG;

    int tt = 0;
    for (int c = 0; c < NCHUNKS; ++c) {
        CP_WAIT(4);                 // x chunk c (and everything older) landed
        __syncthreads();            // everyone done with chunk c-1's buffer

        // stage x chunk c+1 into the buffer just freed
        if (c + 1 < NCHUNKS) {
#pragma unroll
            for (int i = 0; i < 8; ++i) {
                int idx = tid + i * THREADS;
                cp16(sm + SM_X((c + 1) & 1) + (unsigned)(idx * 16), gxp + idx);
            }
        }
        CP_COMMIT();
        gxp += CHUNK_F4;

        const float4* s_x = reinterpret_cast<const float4*>(smem_raw + SM_X(c & 1));

#pragma unroll
        for (int t = 0; t < TITERS; ++t) {
            CP_WAIT(4);             // qw granule tt landed

            const int* s_qw = reinterpret_cast<const int*>(smem_raw + SM_QW(tt & 3))
                              + warp * 128;
            const float4* xbase = s_x + (t * 32 + lane) * 8;
            const int gsel = (c << 1) | (t >> 1);

            int bv[ROWS_PER_WARP];
            float2 sB[ROWS_PER_WARP];
#pragma unroll
            for (int r = 0; r < ROWS_PER_WARP; ++r) {
                bv[r] = s_qw[r * 32 + lane];
                sB[r] = s_sb[r * NG + gsel];
            }

            ull w[ROWS_PER_WARP];
            // even columns (low nibble)
#pragma unroll
            for (int r = 0; r < ROWS_PER_WARP; ++r) {
                float q0 = __int_as_float(0x4B000000 | (bv[r] & 15)) - 8388608.0f;
                PACKW(w[r], fmaf(q0, sB[r].x, sB[r].y));
            }
#pragma unroll
            for (int q = 0; q < 4; ++q) {
                ulonglong2 v = *reinterpret_cast<const ulonglong2*>(xbase + (q ^ xr));
#pragma unroll
                for (int r = 0; r < ROWS_PER_WARP; ++r) {
                    FMA2(acc[r][2 * q],     v.x, w[r]);
                    FMA2(acc[r][2 * q + 1], v.y, w[r]);
                }
            }
            // odd columns (high nibble) — reuse w regs
#pragma unroll
            for (int r = 0; r < ROWS_PER_WARP; ++r) {
                float q1 = __int_as_float(0x4B000000 | ((bv[r] >> 4) & 15)) - 8388608.0f;
                PACKW(w[r], fmaf(q1, sB[r].x, sB[r].y));
            }
#pragma unroll
            for (int q = 0; q < 4; ++q) {
                ulonglong2 v = *reinterpret_cast<const ulonglong2*>(xbase + ((q + 4) ^ xr));
#pragma unroll
                for (int r = 0; r < ROWS_PER_WARP; ++r) {
                    FMA2(acc[r][2 * q],     v.x, w[r]);
                    FMA2(acc[r][2 * q + 1], v.y, w[r]);
                }
            }

            // stage qw granule tt+4 into the slot just consumed (thread-local safety)
            if (tt + 4 < TT_TOTAL) cp16(qdst + (unsigned)((tt & 3) << 11), qsrc);
            qsrc += 32;
            CP_COMMIT();
            ++tt;
        }
    }

    // ---- cross-lane reduction: 64-bit shfl butterfly + packed add ----
#pragma unroll
    for (int r = 0; r < ROWS_PER_WARP; ++r)
#pragma unroll
        for (int k = 0; k < 8; ++k) {
            ull v = acc[r][k];
#pragma unroll
            for (int off = 16; off; off >>= 1) {
                ull u = __shfl_xor_sync(0xffffffffu, v, off);
                ADD2(v, v, u);
            }
            acc[r][k] = v;
        }

    // ---- stage output tile [16 batches][16 cols] in smem, coalesced store ----
    CP_WAIT(0);
    __syncthreads();
    float* so = reinterpret_cast<float*>(smem_raw);
#pragma unroll
    for (int r = 0; r < ROWS_PER_WARP; ++r)
#pragma unroll
        for (int k = 0; k < 8; ++k)
            if (lane == r * 8 + k) {
                int col = warp * ROWS_PER_WARP + r;
                so[(2 * k) * ROWS_PER_BLOCK + col] =
                    __uint_as_float((unsigned)(acc[r][k] & 0xffffffffull));
                so[(2 * k + 1) * ROWS_PER_BLOCK + col] =
                    __uint_as_float((unsigned)(acc[r][k] >> 32));
            }
    __syncthreads();

#pragma unroll
    for (int idx = tid; idx < NB * ROWS_PER_BLOCK; idx += THREADS) {
        int b = idx >> 4, col = idx & 15;
        out[b * OUTF + rb0 + col] = so[idx] + bias[rb0 + col];
    }
}

extern "C" void kernel_launch(void* const* d_in, const int* in_sizes, int n_in,
                              void* d_out, int out_size) {
    const float* x      = (const float*)d_in[0];
    const int*   qw     = (const int*)d_in[1];
    const float* scales = (const float*)d_in[2];
    const float* zeros  = (const float*)d_in[3];
    const float* bias   = (const float*)d_in[4];
    float*       out    = (float*)d_out;

    prep_kernel<<<64 + (OUTF * NG) / 256, 256>>>(x, scales, zeros);
    gptq_main_kernel<<<NBLOCKS, THREADS>>>(qw, bias, out);
}